// round 1
// baseline (speedup 1.0000x reference)
#include <cuda_runtime.h>
#include <math.h>
#include <stdint.h>

// ---------------------------------------------------------------------------
// QuaternionLSTM single step, h0=c0=0:
//   W1[f, 4*h+g] = quaternion-expanded wx kernel (gate g interleaved per h)
//   Z = x @ W1 + b1 ; ft,it,ot=sigmoid(z0..2), at=z3
//   H[b,h] = sigmoid(z2)*tanh( sigmoid(z1)*tanh(z3) )        (c0=0, f-gate drops)
//   out = H @ fco_w + fco_b
// ---------------------------------------------------------------------------

#define F_DIM 1024
#define H_DIM 256
#define N1    1024        // 4 gates * 256
#define B_DIM 32768

__device__ float g_W1[F_DIM * N1];        // 4 MB  [K=1024][N=1024], n = 4*h+g
__device__ float g_b1[N1];
__device__ float g_H[(size_t)B_DIM * H_DIM];  // 32 MB intermediate

// ---- packed dual-fp32 helpers (sm_100+) -----------------------------------
#define FMA_F32X2(d, a, b, c) \
    asm("fma.rn.f32x2 %0, %1, %2, %3;" : "=l"(d) : "l"(a), "l"(b), "l"(c))

__device__ __forceinline__ unsigned long long dup2(float x) {
    unsigned long long r;
    asm("mov.b64 %0, {%1, %1};" : "=l"(r) : "r"(__float_as_uint(x)));
    return r;
}

// ---------------------------------------------------------------------------
// Build W1 from quaternion components.
// Hamilton-product block table (row block q_in, col block q_out):
//   comp[q_in][q_out], sign[q_in][q_out]
// ---------------------------------------------------------------------------
__global__ void build_w1(const float* __restrict__ wr, const float* __restrict__ wi,
                         const float* __restrict__ wj, const float* __restrict__ wk,
                         const float* __restrict__ bx) {
    int idx = blockIdx.x * blockDim.x + threadIdx.x;
    if (idx >= F_DIM * N1) return;
    int n = idx & (N1 - 1);
    int f = idx >> 10;
    int g  = n & 3;
    int h  = n >> 2;
    int qout = h >> 6;        // h / 64
    int h4   = h & 63;
    int qin  = f >> 8;        // f / 256
    int f4   = f & 255;

    const int   ci[4][4] = {{0,1,2,3},{1,0,3,2},{2,3,0,1},{3,2,1,0}};
    const float sg[4][4] = {{ 1.f, 1.f, 1.f, 1.f},
                            {-1.f, 1.f, 1.f,-1.f},
                            {-1.f,-1.f, 1.f, 1.f},
                            {-1.f, 1.f,-1.f, 1.f}};
    const float* arr[4] = {wr, wi, wj, wk};
    // each wx_* is [4 gates][256][64]
    float v = arr[ci[qin][qout]][g * (256 * 64) + f4 * 64 + h4] * sg[qin][qout];
    g_W1[(size_t)f * N1 + n] = v;
    if (f == 0) g_b1[n] = bx[g * H_DIM + h];
}

// ---------------------------------------------------------------------------
// GEMM1 + LSTM epilogue: Z = x @ W1, H = ot*tanh(it*tanh(at))
// 128x128x8 tile, 256 threads, 8x8 per thread via packed f32x2 FMA.
// ---------------------------------------------------------------------------
__global__ __launch_bounds__(256)
void lstm_gemm(const float* __restrict__ A) {
    const int K = F_DIM, N = N1;
    __shared__ float As[8][128];
    __shared__ float Bs[8][128];

    int tid = threadIdx.x;
    int tx = tid & 15, ty = tid >> 4;
    int rowBase = blockIdx.y * 128;
    int colBase = blockIdx.x * 128;

    int aRow = tid >> 1,  aCol = (tid & 1) << 2;
    int bRow = tid >> 5,  bCol = (tid & 31) << 2;

    const float* Ap = A + (size_t)(rowBase + aRow) * K + aCol;
    const float* Bp = g_W1 + (size_t)bRow * N + colBase + bCol;

    unsigned long long acc[8][4];
#pragma unroll
    for (int r = 0; r < 8; r++)
#pragma unroll
        for (int c = 0; c < 4; c++) acc[r][c] = 0ULL;

    for (int k0 = 0; k0 < K; k0 += 8) {
        float4 av = *(const float4*)(Ap + k0);
        float4 bv = *(const float4*)(Bp + (size_t)k0 * N);
        As[aCol + 0][aRow] = av.x;
        As[aCol + 1][aRow] = av.y;
        As[aCol + 2][aRow] = av.z;
        As[aCol + 3][aRow] = av.w;
        *(float4*)&Bs[bRow][bCol] = bv;
        __syncthreads();
#pragma unroll
        for (int k = 0; k < 8; k++) {
            float4 alo = *(const float4*)&As[k][ty * 4];
            float4 ahi = *(const float4*)&As[k][64 + ty * 4];
            ulonglong2 blo = *(const ulonglong2*)&Bs[k][tx * 4];
            ulonglong2 bhi = *(const ulonglong2*)&Bs[k][64 + tx * 4];
            float ar[8] = {alo.x, alo.y, alo.z, alo.w, ahi.x, ahi.y, ahi.z, ahi.w};
            unsigned long long bp[4] = {blo.x, blo.y, bhi.x, bhi.y};
#pragma unroll
            for (int r = 0; r < 8; r++) {
                unsigned long long ad = dup2(ar[r]);
#pragma unroll
                for (int c = 0; c < 4; c++)
                    FMA_F32X2(acc[r][c], ad, bp[c], acc[r][c]);
            }
        }
        __syncthreads();
    }

    // epilogue: each 4-consecutive-column group = gates {f,i,o,a} of one h
#pragma unroll
    for (int r = 0; r < 8; r++) {
        int m = rowBase + (r < 4 ? ty * 4 + r : 64 + ty * 4 + (r - 4));
#pragma unroll
        for (int grp = 0; grp < 2; grp++) {
            int ncol = colBase + grp * 64 + tx * 4;   // = 4*h
            uint2 p0 = *(uint2*)&acc[r][grp * 2 + 0];
            uint2 p1 = *(uint2*)&acc[r][grp * 2 + 1];
            float z0 = __uint_as_float(p0.x) + g_b1[ncol + 0];
            float z1 = __uint_as_float(p0.y) + g_b1[ncol + 1];
            float z2 = __uint_as_float(p1.x) + g_b1[ncol + 2];
            float z3 = __uint_as_float(p1.y) + g_b1[ncol + 3];
            (void)z0;  // forget gate multiplies c0 = 0
            float it = 1.f / (1.f + __expf(-z1));
            float ot = 1.f / (1.f + __expf(-z2));
            float cc = it * tanhf(z3);
            float hv = ot * tanhf(cc);
            g_H[(size_t)m * H_DIM + (ncol >> 2)] = hv;
        }
    }
}

// ---------------------------------------------------------------------------
// GEMM2: out = H @ fco_w + fco_b   (32768x256 @ 256x256)
// ---------------------------------------------------------------------------
__global__ __launch_bounds__(256)
void out_gemm(const float* __restrict__ Bw, const float* __restrict__ bias,
              float* __restrict__ C) {
    const int K = H_DIM, N = H_DIM;
    __shared__ float As[8][128];
    __shared__ float Bs[8][128];

    int tid = threadIdx.x;
    int tx = tid & 15, ty = tid >> 4;
    int rowBase = blockIdx.y * 128;
    int colBase = blockIdx.x * 128;

    int aRow = tid >> 1,  aCol = (tid & 1) << 2;
    int bRow = tid >> 5,  bCol = (tid & 31) << 2;

    const float* Ap = g_H + (size_t)(rowBase + aRow) * K + aCol;
    const float* Bp = Bw + (size_t)bRow * N + colBase + bCol;

    unsigned long long acc[8][4];
#pragma unroll
    for (int r = 0; r < 8; r++)
#pragma unroll
        for (int c = 0; c < 4; c++) acc[r][c] = 0ULL;

    for (int k0 = 0; k0 < K; k0 += 8) {
        float4 av = *(const float4*)(Ap + k0);
        float4 bv = *(const float4*)(Bp + (size_t)k0 * N);
        As[aCol + 0][aRow] = av.x;
        As[aCol + 1][aRow] = av.y;
        As[aCol + 2][aRow] = av.z;
        As[aCol + 3][aRow] = av.w;
        *(float4*)&Bs[bRow][bCol] = bv;
        __syncthreads();
#pragma unroll
        for (int k = 0; k < 8; k++) {
            float4 alo = *(const float4*)&As[k][ty * 4];
            float4 ahi = *(const float4*)&As[k][64 + ty * 4];
            ulonglong2 blo = *(const ulonglong2*)&Bs[k][tx * 4];
            ulonglong2 bhi = *(const ulonglong2*)&Bs[k][64 + tx * 4];
            float ar[8] = {alo.x, alo.y, alo.z, alo.w, ahi.x, ahi.y, ahi.z, ahi.w};
            unsigned long long bp[4] = {blo.x, blo.y, bhi.x, bhi.y};
#pragma unroll
            for (int r = 0; r < 8; r++) {
                unsigned long long ad = dup2(ar[r]);
#pragma unroll
                for (int c = 0; c < 4; c++)
                    FMA_F32X2(acc[r][c], ad, bp[c], acc[r][c]);
            }
        }
        __syncthreads();
    }

#pragma unroll
    for (int r = 0; r < 8; r++) {
        int m = rowBase + (r < 4 ? ty * 4 + r : 64 + ty * 4 + (r - 4));
#pragma unroll
        for (int grp = 0; grp < 2; grp++) {
            int ncol = colBase + grp * 64 + tx * 4;
            uint2 p0 = *(uint2*)&acc[r][grp * 2 + 0];
            uint2 p1 = *(uint2*)&acc[r][grp * 2 + 1];
            float4 o;
            o.x = __uint_as_float(p0.x) + bias[ncol + 0];
            o.y = __uint_as_float(p0.y) + bias[ncol + 1];
            o.z = __uint_as_float(p1.x) + bias[ncol + 2];
            o.w = __uint_as_float(p1.y) + bias[ncol + 3];
            *(float4*)&C[(size_t)m * N + ncol] = o;
        }
    }
}

// ---------------------------------------------------------------------------
extern "C" void kernel_launch(void* const* d_in, const int* in_sizes, int n_in,
                              void* d_out, int out_size) {
    const float* x    = (const float*)d_in[0];
    const float* wx_r = (const float*)d_in[1];
    const float* wx_i = (const float*)d_in[2];
    const float* wx_j = (const float*)d_in[3];
    const float* wx_k = (const float*)d_in[4];
    const float* bx   = (const float*)d_in[5];
    // d_in[6..9] = uh_* : unused, h0 = 0 exactly
    const float* fco_w = (const float*)d_in[10];
    const float* fco_b = (const float*)d_in[11];
    float* out = (float*)d_out;

    build_w1<<<(F_DIM * N1 + 255) / 256, 256>>>(wx_r, wx_i, wx_j, wx_k, bx);
    lstm_gemm<<<dim3(N1 / 128, B_DIM / 128), 256>>>(x);
    out_gemm<<<dim3(H_DIM / 128, B_DIM / 128), 256>>>(fco_w, fco_b, out);
}

// round 3
// speedup vs baseline: 1.8597x; 1.8597x over previous
#include <cuda_runtime.h>
#include <cuda_bf16.h>
#include <stdint.h>

// ============================================================================
// QuaternionLSTM single step, h0=c0=0 (uh_* dead; f-gate multiplies c0=0):
//   Z = x @ W1 + b1  (W1 = quaternion-expanded wx, custom column permutation)
//   H = sigmoid(z_o) * tanh( sigmoid(z_i) * tanh(z_a) )
//   out = H @ fco_w + fco_b
// Tensor cores via mma.sync bf16 (sm_103 base target — tcgen05 PTX rejected
// by this harness's ptxas target). fp32 accuracy via hi/lo bf16 3-term split.
//
// Column permutation: ncol(h,g) = (h>>2)*16 + (g>>1)*8 + (h&3)*2 + (g&1)
// -> in m16n8k16 accum layout, one thread holds all 4 gates of one h.
// ============================================================================

#define B_DIM 32768
#define F_DIM 1024
#define H_DIM 256
#define N1    1024

__device__ __align__(16) __nv_bfloat16 g_xhi[(size_t)B_DIM * F_DIM];
__device__ __align__(16) __nv_bfloat16 g_xlo[(size_t)B_DIM * F_DIM];
__device__ __align__(16) __nv_bfloat16 g_w1hi[F_DIM * N1];   // [k][n_perm]
__device__ __align__(16) __nv_bfloat16 g_w1lo[F_DIM * N1];
__device__ float g_b1[N1];                                   // permuted cols
__device__ __align__(16) __nv_bfloat16 g_hhi[(size_t)B_DIM * H_DIM];
__device__ __align__(16) __nv_bfloat16 g_hlo[(size_t)B_DIM * H_DIM];
__device__ __align__(16) __nv_bfloat16 g_f2hi[H_DIM * H_DIM]; // [k][n]
__device__ __align__(16) __nv_bfloat16 g_f2lo[H_DIM * H_DIM];

// ---------------------------------------------------------------------------
__device__ __forceinline__ uint32_t smem_u32(const void* p) {
    uint32_t a;
    asm("{ .reg .u64 t; cvta.to.shared.u64 t, %1; cvt.u32.u64 %0, t; }" : "=r"(a) : "l"(p));
    return a;
}

#define LDSM_X4(r, a) \
    asm volatile("ldmatrix.sync.aligned.m8n8.x4.shared.b16 {%0,%1,%2,%3}, [%4];" \
        : "=r"((r)[0]), "=r"((r)[1]), "=r"((r)[2]), "=r"((r)[3]) : "r"(a))
#define LDSM_X4T(r, a) \
    asm volatile("ldmatrix.sync.aligned.m8n8.x4.trans.shared.b16 {%0,%1,%2,%3}, [%4];" \
        : "=r"((r)[0]), "=r"((r)[1]), "=r"((r)[2]), "=r"((r)[3]) : "r"(a))
#define MMA_BF16(d, a, b) \
    asm volatile("mma.sync.aligned.m16n8k16.row.col.f32.bf16.bf16.f32 " \
        "{%0,%1,%2,%3}, {%4,%5,%6,%7}, {%8,%9}, {%0,%1,%2,%3};" \
        : "+f"((d)[0]), "+f"((d)[1]), "+f"((d)[2]), "+f"((d)[3]) \
        : "r"((a)[0]), "r"((a)[1]), "r"((a)[2]), "r"((a)[3]), "r"((b)[0]), "r"((b)[1]))
#define CP_ASYNC16(dst, src) \
    asm volatile("cp.async.cg.shared.global [%0], [%1], 16;" :: "r"(dst), "l"(src) : "memory")
#define CP_COMMIT() asm volatile("cp.async.commit_group;" ::: "memory")
#define CP_WAIT(n)  asm volatile("cp.async.wait_group %0;" :: "n"(n) : "memory")

__device__ __forceinline__ float fsigm(float z) {
    return __fdividef(1.f, 1.f + __expf(-z));
}
__device__ __forceinline__ float ftanh(float x) {
    float xc = fminf(fmaxf(x, -15.f), 15.f);
    float e = __expf(2.f * xc);
    return __fdividef(e - 1.f, e + 1.f);
}

// ---------------------------------------------------------------------------
// Prep kernels
// ---------------------------------------------------------------------------
__global__ void split_x(const float* __restrict__ x) {
    size_t i = ((size_t)blockIdx.x * blockDim.x + threadIdx.x) * 4;
    float4 v = *(const float4*)(x + i);
    __nv_bfloat16 h[4], l[4];
    float vv[4] = {v.x, v.y, v.z, v.w};
#pragma unroll
    for (int j = 0; j < 4; j++) {
        h[j] = __float2bfloat16(vv[j]);
        l[j] = __float2bfloat16(vv[j] - __bfloat162float(h[j]));
    }
    *(uint2*)&g_xhi[i] = *(uint2*)h;
    *(uint2*)&g_xlo[i] = *(uint2*)l;
}

__global__ void build_w1(const float* __restrict__ wr, const float* __restrict__ wi,
                         const float* __restrict__ wj, const float* __restrict__ wk,
                         const float* __restrict__ bx) {
    int idx = blockIdx.x * blockDim.x + threadIdx.x;  // over F_DIM * N1
    int f = idx >> 10;
    int nn = idx & 1023;
    int h = nn >> 2, g = nn & 3;
    int qout = h >> 6, h4 = h & 63;
    int qin = f >> 8, f4 = f & 255;
    const int   ci[4][4] = {{0,1,2,3},{1,0,3,2},{2,3,0,1},{3,2,1,0}};
    const float sg[4][4] = {{ 1.f, 1.f, 1.f, 1.f},
                            {-1.f, 1.f, 1.f,-1.f},
                            {-1.f,-1.f, 1.f, 1.f},
                            {-1.f, 1.f,-1.f, 1.f}};
    const float* arr[4] = {wr, wi, wj, wk};
    float v = arr[ci[qin][qout]][g * (256 * 64) + f4 * 64 + h4] * sg[qin][qout];
    int ncol = ((h >> 2) << 4) + ((g >> 1) << 3) + ((h & 3) << 1) + (g & 1);
    __nv_bfloat16 hi = __float2bfloat16(v);
    g_w1hi[f * N1 + ncol] = hi;
    g_w1lo[f * N1 + ncol] = __float2bfloat16(v - __bfloat162float(hi));
    if (f == 0) g_b1[ncol] = bx[g * H_DIM + h];
}

__global__ void split_fco(const float* __restrict__ w) {
    int idx = blockIdx.x * blockDim.x + threadIdx.x;  // over 65536, [k][n]
    float v = w[idx];
    __nv_bfloat16 hi = __float2bfloat16(v);
    g_f2hi[idx] = hi;
    g_f2lo[idx] = __float2bfloat16(v - __bfloat162float(hi));
}

// ---------------------------------------------------------------------------
// mma.sync GEMM: CTA tile 128x128, K-chunk 32, 8 warps (warp tile 64x32),
// bf16 hi/lo 3-term, double-buffered cp.async.
// SMEM per stage: A[2][128][40]bf16 (20480B) + B[2][32][136]bf16 (17408B)
// ---------------------------------------------------------------------------
#define STAGE_BYTES 37888
#define A_COMP      10240
#define B_OFF       20480
#define B_COMP      8704
#define SMEM_TOT    (2 * STAGE_BYTES)

template<int KD, int NB, bool LSTM>
__global__ __launch_bounds__(256, 1)
void gemm_mma(const float* __restrict__ biasg, float* __restrict__ outp) {
    constexpr int NSTEPS = KD / 32;
    extern __shared__ __align__(128) char smem[];
    const uint32_t sb = smem_u32(smem);
    const int tid = threadIdx.x, lane = tid & 31, wid = tid >> 5;
    const int wm = wid >> 2, wn = wid & 3;
    const int rowBase = blockIdx.y * 128, colBase = blockIdx.x * 128;

    const __nv_bfloat16* Ahi = LSTM ? g_xhi : g_hhi;
    const __nv_bfloat16* Alo = LSTM ? g_xlo : g_hlo;
    const __nv_bfloat16* Bhi = LSTM ? g_w1hi : g_f2hi;
    const __nv_bfloat16* Blo = LSTM ? g_w1lo : g_f2lo;

    auto load_stage = [&](int buf, int k0) {
        uint32_t base = sb + buf * STAGE_BYTES;
#pragma unroll
        for (int i = 0; i < 8; i++) {
            int g = i * 256 + tid;
            const __nv_bfloat16* src;
            uint32_t dst;
            if (g < 1024) {                       // A: [2comp][128 rows][4 x16B]
                int comp = g >> 9, rem = g & 511, row = rem >> 2, c16 = rem & 3;
                src = (comp ? Alo : Ahi) + (size_t)(rowBase + row) * KD + k0 + c16 * 8;
                dst = base + comp * A_COMP + row * 80 + c16 * 16;
            } else {                              // B: [2comp][32 rows][16 x16B]
                int gb = g - 1024;
                int comp = gb >> 9, rem = gb & 511, row = rem >> 4, c16 = rem & 15;
                src = (comp ? Blo : Bhi) + (size_t)(k0 + row) * NB + colBase + c16 * 8;
                dst = base + B_OFF + comp * B_COMP + row * 272 + c16 * 16;
            }
            CP_ASYNC16(dst, src);
        }
        CP_COMMIT();
    };

    float acc[4][4][4];
#pragma unroll
    for (int a = 0; a < 4; a++)
#pragma unroll
        for (int b = 0; b < 4; b++)
#pragma unroll
            for (int c = 0; c < 4; c++) acc[a][b][c] = 0.f;

    load_stage(0, 0);

#pragma unroll 1
    for (int s = 0; s < NSTEPS; s++) {
        if (s + 1 < NSTEPS) { load_stage((s + 1) & 1, (s + 1) * 32); CP_WAIT(1); }
        else                { CP_WAIT(0); }
        __syncthreads();
        uint32_t base = sb + (s & 1) * STAGE_BYTES;
#pragma unroll
        for (int kk = 0; kk < 2; kk++) {
            uint32_t ah[4][4], al[4][4], bh[2][4], bl[2][4];
#pragma unroll
            for (int mi = 0; mi < 4; mi++) {
                uint32_t addr = base + (wm * 64 + mi * 16 + (lane & 15)) * 80
                              + (kk * 16 + (lane >> 4) * 8) * 2;
                LDSM_X4(ah[mi], addr);
                LDSM_X4(al[mi], addr + A_COMP);
            }
#pragma unroll
            for (int p = 0; p < 2; p++) {
                uint32_t addr = base + B_OFF + (kk * 16 + (lane & 15)) * 272
                              + (wn * 32 + p * 16 + (lane >> 4) * 8) * 2;
                LDSM_X4T(bh[p], addr);
                LDSM_X4T(bl[p], addr + B_COMP);
            }
#pragma unroll
            for (int mi = 0; mi < 4; mi++)
#pragma unroll
                for (int ni = 0; ni < 4; ni++) {
                    uint32_t* bfh = &bh[ni >> 1][(ni & 1) * 2];
                    uint32_t* bfl = &bl[ni >> 1][(ni & 1) * 2];
                    MMA_BF16(acc[mi][ni], ah[mi], bfh);
                    MMA_BF16(acc[mi][ni], al[mi], bfh);
                    MMA_BF16(acc[mi][ni], ah[mi], bfl);
                }
        }
        __syncthreads();
    }

    // ------------------------- epilogue (register-local) -------------------
    if (LSTM) {
        float bi[2], bo[2], ba[2];
#pragma unroll
        for (int p = 0; p < 2; p++) {
            int cb = colBase + wn * 32 + p * 16 + (lane & 3) * 2;
            bi[p] = g_b1[cb + 1];
            bo[p] = g_b1[cb + 8];
            ba[p] = g_b1[cb + 9];
        }
#pragma unroll
        for (int mi = 0; mi < 4; mi++) {
            int r0 = rowBase + wm * 64 + mi * 16 + (lane >> 2);
#pragma unroll
            for (int p = 0; p < 2; p++) {
                int hcol = (colBase >> 2) + wn * 8 + p * 4 + (lane & 3);
#pragma unroll
                for (int rr = 0; rr < 2; rr++) {
                    float zi = acc[mi][2 * p][rr * 2 + 1] + bi[p];
                    float zo = acc[mi][2 * p + 1][rr * 2 + 0] + bo[p];
                    float za = acc[mi][2 * p + 1][rr * 2 + 1] + ba[p];
                    float hv = fsigm(zo) * ftanh(fsigm(zi) * ftanh(za));
                    size_t m = (size_t)(r0 + rr * 8);
                    __nv_bfloat16 hb = __float2bfloat16(hv);
                    g_hhi[m * H_DIM + hcol] = hb;
                    g_hlo[m * H_DIM + hcol] =
                        __float2bfloat16(hv - __bfloat162float(hb));
                }
            }
        }
    } else {
#pragma unroll
        for (int mi = 0; mi < 4; mi++) {
            int r0 = rowBase + wm * 64 + mi * 16 + (lane >> 2);
#pragma unroll
            for (int ni = 0; ni < 4; ni++) {
                int col = colBase + wn * 32 + ni * 8 + (lane & 3) * 2;
                float b0 = biasg[col], b1 = biasg[col + 1];
                float2 o0 = {acc[mi][ni][0] + b0, acc[mi][ni][1] + b1};
                float2 o1 = {acc[mi][ni][2] + b0, acc[mi][ni][3] + b1};
                *(float2*)&outp[(size_t)r0 * H_DIM + col] = o0;
                *(float2*)&outp[(size_t)(r0 + 8) * H_DIM + col] = o1;
            }
        }
    }
}

// ---------------------------------------------------------------------------
extern "C" void kernel_launch(void* const* d_in, const int* in_sizes, int n_in,
                              void* d_out, int out_size) {
    const float* x     = (const float*)d_in[0];
    const float* wx_r  = (const float*)d_in[1];
    const float* wx_i  = (const float*)d_in[2];
    const float* wx_j  = (const float*)d_in[3];
    const float* wx_k  = (const float*)d_in[4];
    const float* bx    = (const float*)d_in[5];
    const float* fco_w = (const float*)d_in[10];
    const float* fco_b = (const float*)d_in[11];
    float* out = (float*)d_out;

    split_x<<<(B_DIM * F_DIM / 4) / 256, 256>>>(x);
    build_w1<<<(F_DIM * N1) / 256, 256>>>(wx_r, wx_i, wx_j, wx_k, bx);
    split_fco<<<(H_DIM * H_DIM) / 256, 256>>>(fco_w);

    cudaFuncSetAttribute(gemm_mma<F_DIM, N1, true>,
                         cudaFuncAttributeMaxDynamicSharedMemorySize, SMEM_TOT);
    cudaFuncSetAttribute(gemm_mma<H_DIM, H_DIM, false>,
                         cudaFuncAttributeMaxDynamicSharedMemorySize, SMEM_TOT);

    gemm_mma<F_DIM, N1, true>
        <<<dim3(N1 / 128, B_DIM / 128), 256, SMEM_TOT>>>(nullptr, nullptr);
    gemm_mma<H_DIM, H_DIM, false>
        <<<dim3(H_DIM / 128, B_DIM / 128), 256, SMEM_TOT>>>(fco_b, out);
}

// round 4
// speedup vs baseline: 2.8330x; 1.5234x over previous
#include <cuda_runtime.h>
#include <cuda_fp16.h>
#include <stdint.h>

// ============================================================================
// QuaternionLSTM single step, h0=c0=0 (uh_* dead; f-gate multiplies c0=0):
//   Z = x @ W1 + b1  (W1 = quaternion-expanded wx, custom column permutation)
//   H = sigmoid(z_o) * tanh( sigmoid(z_i) * tanh(z_a) )
//   out = H @ fco_w + fco_b
// mma.sync fp16 (f32 accum), 2-term split: A = hi+lo fp16 (exact), B single
// fp16 -> error ~2^-12. Column permutation keeps LSTM epilogue register-local.
// 2 CTAs/SM, 3-stage cp.async pipeline.
// ============================================================================

#define B_DIM 32768
#define F_DIM 1024
#define H_DIM 256
#define N1    1024

__device__ __align__(16) __half g_xhi[(size_t)B_DIM * F_DIM];
__device__ __align__(16) __half g_xlo[(size_t)B_DIM * F_DIM];
__device__ __align__(16) __half g_w1[F_DIM * N1];            // [k][n_perm]
__device__ float g_b1[N1];                                    // permuted cols
__device__ __align__(16) __half g_hhi[(size_t)B_DIM * H_DIM];
__device__ __align__(16) __half g_hlo[(size_t)B_DIM * H_DIM];
__device__ __align__(16) __half g_f2[H_DIM * H_DIM];          // [k][n]

// ---------------------------------------------------------------------------
__device__ __forceinline__ uint32_t smem_u32(const void* p) {
    uint32_t a;
    asm("{ .reg .u64 t; cvta.to.shared.u64 t, %1; cvt.u32.u64 %0, t; }" : "=r"(a) : "l"(p));
    return a;
}

#define LDSM_X4(r, a) \
    asm volatile("ldmatrix.sync.aligned.m8n8.x4.shared.b16 {%0,%1,%2,%3}, [%4];" \
        : "=r"((r)[0]), "=r"((r)[1]), "=r"((r)[2]), "=r"((r)[3]) : "r"(a))
#define LDSM_X4T(r, a) \
    asm volatile("ldmatrix.sync.aligned.m8n8.x4.trans.shared.b16 {%0,%1,%2,%3}, [%4];" \
        : "=r"((r)[0]), "=r"((r)[1]), "=r"((r)[2]), "=r"((r)[3]) : "r"(a))
#define MMA_F16(d, a, b) \
    asm volatile("mma.sync.aligned.m16n8k16.row.col.f32.f16.f16.f32 " \
        "{%0,%1,%2,%3}, {%4,%5,%6,%7}, {%8,%9}, {%0,%1,%2,%3};" \
        : "+f"((d)[0]), "+f"((d)[1]), "+f"((d)[2]), "+f"((d)[3]) \
        : "r"((a)[0]), "r"((a)[1]), "r"((a)[2]), "r"((a)[3]), "r"((b)[0]), "r"((b)[1]))
#define CP_ASYNC16(dst, src) \
    asm volatile("cp.async.cg.shared.global [%0], [%1], 16;" :: "r"(dst), "l"(src) : "memory")
#define CP_COMMIT() asm volatile("cp.async.commit_group;" ::: "memory")
#define CP_WAIT(n)  asm volatile("cp.async.wait_group %0;" :: "n"(n) : "memory")

__device__ __forceinline__ float fsigm(float z) {
    return __fdividef(1.f, 1.f + __expf(-z));
}
__device__ __forceinline__ float ftanh(float x) {
    float xc = fminf(fmaxf(x, -15.f), 15.f);
    float e = __expf(2.f * xc);
    return __fdividef(e - 1.f, e + 1.f);
}

// ---------------------------------------------------------------------------
// Prep kernels
// ---------------------------------------------------------------------------
__global__ void split_x(const float* __restrict__ x) {
    size_t i = ((size_t)blockIdx.x * blockDim.x + threadIdx.x) * 4;
    float4 v = *(const float4*)(x + i);
    __half h[4], l[4];
    float vv[4] = {v.x, v.y, v.z, v.w};
#pragma unroll
    for (int j = 0; j < 4; j++) {
        h[j] = __float2half(vv[j]);
        l[j] = __float2half(vv[j] - __half2float(h[j]));
    }
    *(uint2*)&g_xhi[i] = *(uint2*)h;
    *(uint2*)&g_xlo[i] = *(uint2*)l;
}

__global__ void build_w1(const float* __restrict__ wr, const float* __restrict__ wi,
                         const float* __restrict__ wj, const float* __restrict__ wk,
                         const float* __restrict__ bx) {
    int idx = blockIdx.x * blockDim.x + threadIdx.x;  // over F_DIM * N1
    int f = idx >> 10;
    int nn = idx & 1023;
    int h = nn >> 2, g = nn & 3;
    int qout = h >> 6, h4 = h & 63;
    int qin = f >> 8, f4 = f & 255;
    const int   ci[4][4] = {{0,1,2,3},{1,0,3,2},{2,3,0,1},{3,2,1,0}};
    const float sg[4][4] = {{ 1.f, 1.f, 1.f, 1.f},
                            {-1.f, 1.f, 1.f,-1.f},
                            {-1.f,-1.f, 1.f, 1.f},
                            {-1.f, 1.f,-1.f, 1.f}};
    const float* arr[4] = {wr, wi, wj, wk};
    float v = arr[ci[qin][qout]][g * (256 * 64) + f4 * 64 + h4] * sg[qin][qout];
    int ncol = ((h >> 2) << 4) + ((g >> 1) << 3) + ((h & 3) << 1) + (g & 1);
    g_w1[f * N1 + ncol] = __float2half(v);
    if (f == 0) g_b1[ncol] = bx[g * H_DIM + h];
}

__global__ void split_fco(const float* __restrict__ w) {
    int idx = blockIdx.x * blockDim.x + threadIdx.x;  // over 65536, [k][n]
    g_f2[idx] = __float2half(w[idx]);
}

// ---------------------------------------------------------------------------
// mma.sync GEMM: CTA tile 128x128, K-chunk 32, 8 warps (warp tile 64x32),
// fp16 2-term (A hi/lo, B single), 3-stage cp.async, 2 CTAs/SM.
// SMEM/stage: A[2][128 rows][40 halves] = 20480B + B[32][136 halves] = 8704B
// ---------------------------------------------------------------------------
#define A_COMP      10240
#define B_OFF       20480
#define STAGE_BYTES 29184
#define NSTAGE      3
#define SMEM_TOT    (NSTAGE * STAGE_BYTES)

template<int KD, int NB, bool LSTM>
__global__ __launch_bounds__(256, 2)
void gemm_mma(const float* __restrict__ biasg, float* __restrict__ outp) {
    constexpr int NSTEPS = KD / 32;
    extern __shared__ __align__(128) char smem[];
    const uint32_t sb = smem_u32(smem);
    const int tid = threadIdx.x, lane = tid & 31, wid = tid >> 5;
    const int wm = wid >> 2, wn = wid & 3;
    const int rowBase = blockIdx.y * 128, colBase = blockIdx.x * 128;

    const __half* Ahi = LSTM ? g_xhi : g_hhi;
    const __half* Alo = LSTM ? g_xlo : g_hlo;
    const __half* Bw  = LSTM ? g_w1  : g_f2;

    // stage loader: A 1024 chunks (16B) + B 512 chunks = 1536; 6/thread
    auto load_stage = [&](int buf, int k0) {
        uint32_t base = sb + buf * STAGE_BYTES;
#pragma unroll
        for (int i = 0; i < 6; i++) {
            int g = i * 256 + tid;
            const __half* src;
            uint32_t dst;
            if (g < 1024) {                 // A: [2 comp][128 rows][4 x 16B]
                int comp = g >> 9, rem = g & 511, row = rem >> 2, c16 = rem & 3;
                src = (comp ? Alo : Ahi) + (size_t)(rowBase + row) * KD + k0 + c16 * 8;
                dst = base + comp * A_COMP + row * 80 + c16 * 16;
            } else {                        // B: [32 rows][16 x 16B]
                int gb = g - 1024;
                int row = gb >> 4, c16 = gb & 15;
                src = Bw + (size_t)(k0 + row) * NB + colBase + c16 * 8;
                dst = base + B_OFF + row * 272 + c16 * 16;
            }
            CP_ASYNC16(dst, src);
        }
        CP_COMMIT();
    };

    float acc[4][4][4];
#pragma unroll
    for (int a = 0; a < 4; a++)
#pragma unroll
        for (int b = 0; b < 4; b++)
#pragma unroll
            for (int c = 0; c < 4; c++) acc[a][b][c] = 0.f;

    load_stage(0, 0);
    load_stage(1, 32);

#pragma unroll 1
    for (int s = 0; s < NSTEPS; s++) {
        if (s + 2 < NSTEPS) { load_stage((s + 2) % 3, (s + 2) * 32); CP_WAIT(2); }
        else if (s + 1 < NSTEPS) { CP_WAIT(1); }
        else { CP_WAIT(0); }
        __syncthreads();

        uint32_t base = sb + (s % 3) * STAGE_BYTES;
#pragma unroll
        for (int kk = 0; kk < 2; kk++) {
            uint32_t bh[2][4];
#pragma unroll
            for (int p = 0; p < 2; p++) {
                uint32_t addr = base + B_OFF + (kk * 16 + (lane & 15)) * 272
                              + (wn * 32 + p * 16 + (lane >> 4) * 8) * 2;
                LDSM_X4T(bh[p], addr);
            }
#pragma unroll
            for (int half = 0; half < 2; half++) {
                uint32_t ah[2][4], al[2][4];
#pragma unroll
                for (int m2 = 0; m2 < 2; m2++) {
                    int mi = half * 2 + m2;
                    uint32_t addr = base + (wm * 64 + mi * 16 + (lane & 15)) * 80
                                  + (kk * 16 + (lane >> 4) * 8) * 2;
                    LDSM_X4(ah[m2], addr);
                    LDSM_X4(al[m2], addr + A_COMP);
                }
#pragma unroll
                for (int m2 = 0; m2 < 2; m2++)
#pragma unroll
                    for (int ni = 0; ni < 4; ni++) {
                        uint32_t* bf = &bh[ni >> 1][(ni & 1) * 2];
                        MMA_F16(acc[half * 2 + m2][ni], ah[m2], bf);
                        MMA_F16(acc[half * 2 + m2][ni], al[m2], bf);
                    }
            }
        }
        __syncthreads();
    }

    // ------------------------- epilogue (register-local) -------------------
    if (LSTM) {
        float bi[2], bo[2], ba[2];
#pragma unroll
        for (int p = 0; p < 2; p++) {
            int cb = colBase + wn * 32 + p * 16 + (lane & 3) * 2;
            bi[p] = g_b1[cb + 1];
            bo[p] = g_b1[cb + 8];
            ba[p] = g_b1[cb + 9];
        }
#pragma unroll
        for (int mi = 0; mi < 4; mi++) {
            int r0 = rowBase + wm * 64 + mi * 16 + (lane >> 2);
#pragma unroll
            for (int p = 0; p < 2; p++) {
                int hcol = (colBase >> 2) + wn * 8 + p * 4 + (lane & 3);
#pragma unroll
                for (int rr = 0; rr < 2; rr++) {
                    float zi = acc[mi][2 * p][rr * 2 + 1] + bi[p];
                    float zo = acc[mi][2 * p + 1][rr * 2 + 0] + bo[p];
                    float za = acc[mi][2 * p + 1][rr * 2 + 1] + ba[p];
                    float hv = fsigm(zo) * ftanh(fsigm(zi) * ftanh(za));
                    size_t m = (size_t)(r0 + rr * 8);
                    __half hb = __float2half(hv);
                    g_hhi[m * H_DIM + hcol] = hb;
                    g_hlo[m * H_DIM + hcol] = __float2half(hv - __half2float(hb));
                }
            }
        }
    } else {
#pragma unroll
        for (int mi = 0; mi < 4; mi++) {
            int r0 = rowBase + wm * 64 + mi * 16 + (lane >> 2);
#pragma unroll
            for (int ni = 0; ni < 4; ni++) {
                int col = colBase + wn * 32 + ni * 8 + (lane & 3) * 2;
                float b0 = biasg[col], b1 = biasg[col + 1];
                float2 o0 = {acc[mi][ni][0] + b0, acc[mi][ni][1] + b1};
                float2 o1 = {acc[mi][ni][2] + b0, acc[mi][ni][3] + b1};
                *(float2*)&outp[(size_t)r0 * H_DIM + col] = o0;
                *(float2*)&outp[(size_t)(r0 + 8) * H_DIM + col] = o1;
            }
        }
    }
}

// ---------------------------------------------------------------------------
extern "C" void kernel_launch(void* const* d_in, const int* in_sizes, int n_in,
                              void* d_out, int out_size) {
    const float* x     = (const float*)d_in[0];
    const float* wx_r  = (const float*)d_in[1];
    const float* wx_i  = (const float*)d_in[2];
    const float* wx_j  = (const float*)d_in[3];
    const float* wx_k  = (const float*)d_in[4];
    const float* bx    = (const float*)d_in[5];
    const float* fco_w = (const float*)d_in[10];
    const float* fco_b = (const float*)d_in[11];
    float* out = (float*)d_out;

    split_x<<<(B_DIM * F_DIM / 4) / 256, 256>>>(x);
    build_w1<<<(F_DIM * N1) / 256, 256>>>(wx_r, wx_i, wx_j, wx_k, bx);
    split_fco<<<(H_DIM * H_DIM) / 256, 256>>>(fco_w);

    cudaFuncSetAttribute(gemm_mma<F_DIM, N1, true>,
                         cudaFuncAttributeMaxDynamicSharedMemorySize, SMEM_TOT);
    cudaFuncSetAttribute(gemm_mma<H_DIM, H_DIM, false>,
                         cudaFuncAttributeMaxDynamicSharedMemorySize, SMEM_TOT);

    gemm_mma<F_DIM, N1, true>
        <<<dim3(N1 / 128, B_DIM / 128), 256, SMEM_TOT>>>(nullptr, nullptr);
    gemm_mma<H_DIM, H_DIM, false>
        <<<dim3(H_DIM / 128, B_DIM / 128), 256, SMEM_TOT>>>(fco_b, out);
}

// round 5
// speedup vs baseline: 3.5173x; 1.2415x over previous
#include <cuda_runtime.h>
#include <cuda_fp16.h>
#include <stdint.h>

// ============================================================================
// QuaternionLSTM single step, h0=c0=0 (uh_* dead; forget gate multiplies c0=0
// so its 256 GEMM columns are DROPPED):
//   Z = x @ W1 + b1  (W1 = quaternion-expanded wx, gates {i,o,a} only, N=768)
//   H = sigmoid(z_o) * tanh( sigmoid(z_i) * tanh(z_a) )
//   out = H @ fco_w + fco_b
// mma.sync fp16 (f32 accum), 2-term split: A = hi+lo fp16 (exact to 2^-22),
// B single fp16 (error ~2^-12 -> rel_err ~3e-4).
// Column layout ncol = (h>>3)*24 + gate*8 + (h&7) keeps epilogue register-local.
// ============================================================================

#define B_DIM 32768
#define F_DIM 1024
#define H_DIM 256
#define N1G   768            // 3 gates x 256

__device__ __align__(16) __half g_xhi[(size_t)B_DIM * F_DIM];
__device__ __align__(16) __half g_xlo[(size_t)B_DIM * F_DIM];
__device__ __align__(16) __half g_w1[F_DIM * N1G];           // [k][n_perm]
__device__ float g_b1[N1G];                                   // permuted cols
__device__ __align__(16) __half g_hhi[(size_t)B_DIM * H_DIM];
__device__ __align__(16) __half g_hlo[(size_t)B_DIM * H_DIM];
__device__ __align__(16) __half g_f2[H_DIM * H_DIM];          // [k][n]

// ---------------------------------------------------------------------------
__device__ __forceinline__ uint32_t smem_u32(const void* p) {
    uint32_t a;
    asm("{ .reg .u64 t; cvta.to.shared.u64 t, %1; cvt.u32.u64 %0, t; }" : "=r"(a) : "l"(p));
    return a;
}

#define LDSM_X4(r, a) \
    asm volatile("ldmatrix.sync.aligned.m8n8.x4.shared.b16 {%0,%1,%2,%3}, [%4];" \
        : "=r"((r)[0]), "=r"((r)[1]), "=r"((r)[2]), "=r"((r)[3]) : "r"(a))
#define LDSM_X4T(r, a) \
    asm volatile("ldmatrix.sync.aligned.m8n8.x4.trans.shared.b16 {%0,%1,%2,%3}, [%4];" \
        : "=r"((r)[0]), "=r"((r)[1]), "=r"((r)[2]), "=r"((r)[3]) : "r"(a))
#define LDSM_X2T(r, a) \
    asm volatile("ldmatrix.sync.aligned.m8n8.x2.trans.shared.b16 {%0,%1}, [%2];" \
        : "=r"((r)[0]), "=r"((r)[1]) : "r"(a))
#define MMA_F16(d, a, b) \
    asm volatile("mma.sync.aligned.m16n8k16.row.col.f32.f16.f16.f32 " \
        "{%0,%1,%2,%3}, {%4,%5,%6,%7}, {%8,%9}, {%0,%1,%2,%3};" \
        : "+f"((d)[0]), "+f"((d)[1]), "+f"((d)[2]), "+f"((d)[3]) \
        : "r"((a)[0]), "r"((a)[1]), "r"((a)[2]), "r"((a)[3]), "r"((b)[0]), "r"((b)[1]))
#define CP_ASYNC16(dst, src) \
    asm volatile("cp.async.cg.shared.global [%0], [%1], 16;" :: "r"(dst), "l"(src) : "memory")
#define CP_COMMIT() asm volatile("cp.async.commit_group;" ::: "memory")
#define CP_WAIT(n)  asm volatile("cp.async.wait_group %0;" :: "n"(n) : "memory")

__device__ __forceinline__ float fsigm(float z) {
    return __fdividef(1.f, 1.f + __expf(-z));
}
__device__ __forceinline__ float ftanh(float x) {
    float xc = fminf(fmaxf(x, -15.f), 15.f);
    float e = __expf(2.f * xc);
    return __fdividef(e - 1.f, e + 1.f);
}

// ---------------------------------------------------------------------------
// Prep kernels
// ---------------------------------------------------------------------------
__global__ void split_x(const float* __restrict__ x) {
    size_t i = ((size_t)blockIdx.x * blockDim.x + threadIdx.x) * 4;
    float4 v = *(const float4*)(x + i);
    __half h[4], l[4];
    float vv[4] = {v.x, v.y, v.z, v.w};
#pragma unroll
    for (int j = 0; j < 4; j++) {
        h[j] = __float2half(vv[j]);
        l[j] = __float2half(vv[j] - __half2float(h[j]));
    }
    *(uint2*)&g_xhi[i] = *(uint2*)h;
    *(uint2*)&g_xlo[i] = *(uint2*)l;
}

// W1 columns: ncol = blk*24 + g1*8 + hh ;  h = blk*8+hh ; gate = g1+1 (i,o,a)
__global__ void build_w1(const float* __restrict__ wr, const float* __restrict__ wi,
                         const float* __restrict__ wj, const float* __restrict__ wk,
                         const float* __restrict__ bx) {
    int idx = blockIdx.x * blockDim.x + threadIdx.x;  // over F_DIM * N1G
    int f = idx / N1G;
    int rem = idx - f * N1G;
    int blk = rem / 24;
    int r24 = rem - blk * 24;
    int g1 = r24 >> 3, hh = r24 & 7;
    int h = blk * 8 + hh;
    int gate = g1 + 1;                      // skip forget gate (index 0)
    int qout = h >> 6, h4 = h & 63;
    int qin = f >> 8, f4 = f & 255;
    const int   ci[4][4] = {{0,1,2,3},{1,0,3,2},{2,3,0,1},{3,2,1,0}};
    const float sg[4][4] = {{ 1.f, 1.f, 1.f, 1.f},
                            {-1.f, 1.f, 1.f,-1.f},
                            {-1.f,-1.f, 1.f, 1.f},
                            {-1.f, 1.f,-1.f, 1.f}};
    const float* arr[4] = {wr, wi, wj, wk};
    float v = arr[ci[qin][qout]][gate * (256 * 64) + f4 * 64 + h4] * sg[qin][qout];
    g_w1[f * N1G + rem] = __float2half(v);
    if (f == 0) g_b1[rem] = bx[gate * H_DIM + h];
}

__global__ void split_fco(const float* __restrict__ w) {
    int idx = blockIdx.x * blockDim.x + threadIdx.x;  // over 65536, [k][n]
    g_f2[idx] = __float2half(w[idx]);
}

// ---------------------------------------------------------------------------
// GEMM1 + LSTM epilogue: CTA 128x96, K-chunk 32, 8 warps (warp tile 64x24),
// 3-stage cp.async, single syncthreads per k-step, 2 CTAs/SM.
// SMEM/stage: A[2comp][128][40h] = 20480B + B[32][136h pitch 272B] = 8704B
// ---------------------------------------------------------------------------
#define A_COMP      10240
#define B_OFF       20480
#define STAGE_BYTES 29184
#define SMEM_TOT    (3 * STAGE_BYTES)

__global__ __launch_bounds__(256, 2)
void gemm1_lstm() {
    constexpr int KD = F_DIM, NSTEPS = KD / 32;
    extern __shared__ __align__(128) char smem[];
    const uint32_t sb = smem_u32(smem);
    const int tid = threadIdx.x, lane = tid & 31, wid = tid >> 5;
    const int wm = wid >> 2, wn = wid & 3;          // wm:0-1 (64 rows), wn:0-3 (24 cols)
    const int rowBase = blockIdx.y * 128, colBase = blockIdx.x * 96;

    // stage loader: A 1024 chunks + B 384 chunks (32 rows x 12 x 16B)
    auto load_stage = [&](int buf, int k0) {
        uint32_t base = sb + buf * STAGE_BYTES;
#pragma unroll
        for (int i = 0; i < 6; i++) {
            int g = i * 256 + tid;
            if (g >= 1408) break;
            const __half* src;
            uint32_t dst;
            if (g < 1024) {                 // A: [2 comp][128 rows][4 x 16B]
                int comp = g >> 9, rem = g & 511, row = rem >> 2, c16 = rem & 3;
                src = (comp ? g_xlo : g_xhi) + (size_t)(rowBase + row) * KD + k0 + c16 * 8;
                dst = base + comp * A_COMP + row * 80 + c16 * 16;
            } else {                        // B: [32 rows][12 x 16B]
                int gb = g - 1024;
                int row = gb / 12, c16 = gb - row * 12;
                src = g_w1 + (size_t)(k0 + row) * N1G + colBase + c16 * 8;
                dst = base + B_OFF + row * 272 + c16 * 16;
            }
            CP_ASYNC16(dst, src);
        }
        CP_COMMIT();
    };

    float acc[4][3][4];
#pragma unroll
    for (int a = 0; a < 4; a++)
#pragma unroll
        for (int b = 0; b < 3; b++)
#pragma unroll
            for (int c = 0; c < 4; c++) acc[a][b][c] = 0.f;

    load_stage(0, 0);
    load_stage(1, 32);

#pragma unroll 1
    for (int s = 0; s < NSTEPS; s++) {
        if (s + 1 < NSTEPS) CP_WAIT(1); else CP_WAIT(0);
        __syncthreads();        // publish buf s to all; release buf s-1 for writes
        if (s + 2 < NSTEPS) load_stage((s + 2) % 3, (s + 2) * 32);

        uint32_t base = sb + (s % 3) * STAGE_BYTES;
#pragma unroll
        for (int kk = 0; kk < 2; kk++) {
            uint32_t b01[4], b2[2];
            uint32_t brow = base + B_OFF + (kk * 16 + (lane & 15)) * 272;
            LDSM_X4T(b01, brow + (wn * 24 + (lane >> 4) * 8) * 2);
            LDSM_X2T(b2,  brow + (wn * 24 + 16) * 2);
#pragma unroll
            for (int half = 0; half < 2; half++) {
                uint32_t ah[2][4], al[2][4];
#pragma unroll
                for (int m2 = 0; m2 < 2; m2++) {
                    int mi = half * 2 + m2;
                    uint32_t addr = base + (wm * 64 + mi * 16 + (lane & 15)) * 80
                                  + (kk * 16 + (lane >> 4) * 8) * 2;
                    LDSM_X4(ah[m2], addr);
                    LDSM_X4(al[m2], addr + A_COMP);
                }
#pragma unroll
                for (int m2 = 0; m2 < 2; m2++) {
                    int mi = half * 2 + m2;
#pragma unroll
                    for (int ni = 0; ni < 3; ni++) {
                        uint32_t* bf = (ni < 2) ? &b01[ni * 2] : b2;
                        MMA_F16(acc[mi][ni], ah[m2], bf);
                        MMA_F16(acc[mi][ni], al[m2], bf);
                    }
                }
            }
        }
    }

    // --------------------- LSTM epilogue (register-local) -------------------
    // ni tile 0 = z_i, 1 = z_o, 2 = z_a of h-block hb = (colBase/24 + wn)*8.
    const int cb = colBase + wn * 24;
    const int c0 = 2 * (lane & 3);
    const int hb = (colBase / 24 + wn) * 8;
    const int h0 = hb + c0;                         // even; h1 = h0 + 1
    float bi0 = g_b1[cb + c0],      bi1 = g_b1[cb + c0 + 1];
    float bo0 = g_b1[cb + 8 + c0],  bo1 = g_b1[cb + 8 + c0 + 1];
    float ba0 = g_b1[cb + 16 + c0], ba1 = g_b1[cb + 16 + c0 + 1];

#pragma unroll
    for (int mi = 0; mi < 4; mi++) {
        int r0 = rowBase + wm * 64 + mi * 16 + (lane >> 2);
#pragma unroll
        for (int rr = 0; rr < 2; rr++) {            // rows r0, r0+8
            float zi0 = acc[mi][0][rr * 2 + 0] + bi0;
            float zi1 = acc[mi][0][rr * 2 + 1] + bi1;
            float zo0 = acc[mi][1][rr * 2 + 0] + bo0;
            float zo1 = acc[mi][1][rr * 2 + 1] + bo1;
            float za0 = acc[mi][2][rr * 2 + 0] + ba0;
            float za1 = acc[mi][2][rr * 2 + 1] + ba1;
            float hv0 = fsigm(zo0) * ftanh(fsigm(zi0) * ftanh(za0));
            float hv1 = fsigm(zo1) * ftanh(fsigm(zi1) * ftanh(za1));
            size_t m = (size_t)(r0 + rr * 8);
            __half h0h = __float2half(hv0), h1h = __float2half(hv1);
            *(__half2*)&g_hhi[m * H_DIM + h0] = __halves2half2(h0h, h1h);
            *(__half2*)&g_hlo[m * H_DIM + h0] = __halves2half2(
                __float2half(hv0 - __half2float(h0h)),
                __float2half(hv1 - __half2float(h1h)));
        }
    }
}

// ---------------------------------------------------------------------------
// GEMM2: out = H @ fco_w + fco_b. CTA 128x128, K=256, warp tile 64x32.
// ---------------------------------------------------------------------------
__global__ __launch_bounds__(256, 2)
void gemm2(const float* __restrict__ biasg, float* __restrict__ outp) {
    constexpr int KD = H_DIM, NB = H_DIM, NSTEPS = KD / 32;
    extern __shared__ __align__(128) char smem[];
    const uint32_t sb = smem_u32(smem);
    const int tid = threadIdx.x, lane = tid & 31, wid = tid >> 5;
    const int wm = wid >> 2, wn = wid & 3;
    const int rowBase = blockIdx.y * 128, colBase = blockIdx.x * 128;

    auto load_stage = [&](int buf, int k0) {
        uint32_t base = sb + buf * STAGE_BYTES;
#pragma unroll
        for (int i = 0; i < 6; i++) {
            int g = i * 256 + tid;
            const __half* src;
            uint32_t dst;
            if (g < 1024) {
                int comp = g >> 9, rem = g & 511, row = rem >> 2, c16 = rem & 3;
                src = (comp ? g_hlo : g_hhi) + (size_t)(rowBase + row) * KD + k0 + c16 * 8;
                dst = base + comp * A_COMP + row * 80 + c16 * 16;
            } else {
                int gb = g - 1024;
                int row = gb >> 4, c16 = gb & 15;
                src = g_f2 + (size_t)(k0 + row) * NB + colBase + c16 * 8;
                dst = base + B_OFF + row * 272 + c16 * 16;
            }
            CP_ASYNC16(dst, src);
        }
        CP_COMMIT();
    };

    float acc[4][4][4];
#pragma unroll
    for (int a = 0; a < 4; a++)
#pragma unroll
        for (int b = 0; b < 4; b++)
#pragma unroll
            for (int c = 0; c < 4; c++) acc[a][b][c] = 0.f;

    load_stage(0, 0);
    load_stage(1, 32);

#pragma unroll 1
    for (int s = 0; s < NSTEPS; s++) {
        if (s + 1 < NSTEPS) CP_WAIT(1); else CP_WAIT(0);
        __syncthreads();
        if (s + 2 < NSTEPS) load_stage((s + 2) % 3, (s + 2) * 32);

        uint32_t base = sb + (s % 3) * STAGE_BYTES;
#pragma unroll
        for (int kk = 0; kk < 2; kk++) {
            uint32_t bh[2][4];
#pragma unroll
            for (int p = 0; p < 2; p++) {
                uint32_t addr = base + B_OFF + (kk * 16 + (lane & 15)) * 272
                              + (wn * 32 + p * 16 + (lane >> 4) * 8) * 2;
                LDSM_X4T(bh[p], addr);
            }
#pragma unroll
            for (int half = 0; half < 2; half++) {
                uint32_t ah[2][4], al[2][4];
#pragma unroll
                for (int m2 = 0; m2 < 2; m2++) {
                    int mi = half * 2 + m2;
                    uint32_t addr = base + (wm * 64 + mi * 16 + (lane & 15)) * 80
                                  + (kk * 16 + (lane >> 4) * 8) * 2;
                    LDSM_X4(ah[m2], addr);
                    LDSM_X4(al[m2], addr + A_COMP);
                }
#pragma unroll
                for (int m2 = 0; m2 < 2; m2++)
#pragma unroll
                    for (int ni = 0; ni < 4; ni++) {
                        uint32_t* bf = &bh[ni >> 1][(ni & 1) * 2];
                        MMA_F16(acc[half * 2 + m2][ni], ah[m2], bf);
                        MMA_F16(acc[half * 2 + m2][ni], al[m2], bf);
                    }
            }
        }
    }

#pragma unroll
    for (int mi = 0; mi < 4; mi++) {
        int r0 = rowBase + wm * 64 + mi * 16 + (lane >> 2);
#pragma unroll
        for (int ni = 0; ni < 4; ni++) {
            int col = colBase + wn * 32 + ni * 8 + (lane & 3) * 2;
            float b0 = biasg[col], b1 = biasg[col + 1];
            float2 o0 = {acc[mi][ni][0] + b0, acc[mi][ni][1] + b1};
            float2 o1 = {acc[mi][ni][2] + b0, acc[mi][ni][3] + b1};
            *(float2*)&outp[(size_t)r0 * NB + col] = o0;
            *(float2*)&outp[(size_t)(r0 + 8) * NB + col] = o1;
        }
    }
}

// ---------------------------------------------------------------------------
extern "C" void kernel_launch(void* const* d_in, const int* in_sizes, int n_in,
                              void* d_out, int out_size) {
    const float* x     = (const float*)d_in[0];
    const float* wx_r  = (const float*)d_in[1];
    const float* wx_i  = (const float*)d_in[2];
    const float* wx_j  = (const float*)d_in[3];
    const float* wx_k  = (const float*)d_in[4];
    const float* bx    = (const float*)d_in[5];
    const float* fco_w = (const float*)d_in[10];
    const float* fco_b = (const float*)d_in[11];
    float* out = (float*)d_out;

    split_x<<<(B_DIM * F_DIM / 4) / 256, 256>>>(x);
    build_w1<<<(F_DIM * N1G) / 256, 256>>>(wx_r, wx_i, wx_j, wx_k, bx);
    split_fco<<<(H_DIM * H_DIM) / 256, 256>>>(fco_w);

    cudaFuncSetAttribute(gemm1_lstm,
                         cudaFuncAttributeMaxDynamicSharedMemorySize, SMEM_TOT);
    cudaFuncSetAttribute(gemm2,
                         cudaFuncAttributeMaxDynamicSharedMemorySize, SMEM_TOT);

    gemm1_lstm<<<dim3(N1G / 96, B_DIM / 128), 256, SMEM_TOT>>>();
    gemm2<<<dim3(H_DIM / 128, B_DIM / 128), 256, SMEM_TOT>>>(fco_b, out);
}

// round 6
// speedup vs baseline: 6.0452x; 1.7187x over previous
#include <cuda_runtime.h>
#include <cuda_fp16.h>
#include <stdint.h>

// ============================================================================
// QuaternionLSTM single step, h0=c0=0 (uh_* dead; forget-gate columns dropped):
//   Z = x @ W1 + b1  (W1 = quaternion-expanded wx, gates {i,o,a}, N=768)
//   H = sigmoid(z_o) * tanh( sigmoid(z_i) * tanh(z_a) )
//   out = H @ fco_w + fco_b
// Single-fp16 operands both sides (quantization errors add in quadrature,
// ~5.5e-4 < 1e-3), f32 accum. Warp tile 64x48 cuts smem bytes/MAC (crossbar
// was the binding constraint at 55% tensor util).
// Column layout ncol = (h>>3)*24 + gate*8 + (h&7): epilogue register-local.
// ============================================================================

#define B_DIM 32768
#define F_DIM 1024
#define H_DIM 256
#define N1G   768            // 3 gates x 256

__device__ __align__(16) __half g_xh[(size_t)B_DIM * F_DIM];
__device__ __align__(16) __half g_w1[F_DIM * N1G];           // [k][n_perm]
__device__ float g_b1[N1G];
__device__ __align__(16) __half g_h[(size_t)B_DIM * H_DIM];
__device__ __align__(16) __half g_f2[H_DIM * H_DIM];          // [k][n]

// ---------------------------------------------------------------------------
__device__ __forceinline__ uint32_t smem_u32(const void* p) {
    uint32_t a;
    asm("{ .reg .u64 t; cvta.to.shared.u64 t, %1; cvt.u32.u64 %0, t; }" : "=r"(a) : "l"(p));
    return a;
}

#define LDSM_X4(r, a) \
    asm volatile("ldmatrix.sync.aligned.m8n8.x4.shared.b16 {%0,%1,%2,%3}, [%4];" \
        : "=r"((r)[0]), "=r"((r)[1]), "=r"((r)[2]), "=r"((r)[3]) : "r"(a))
#define LDSM_X4T(r, a) \
    asm volatile("ldmatrix.sync.aligned.m8n8.x4.trans.shared.b16 {%0,%1,%2,%3}, [%4];" \
        : "=r"((r)[0]), "=r"((r)[1]), "=r"((r)[2]), "=r"((r)[3]) : "r"(a))
#define MMA_F16(d, a, b) \
    asm volatile("mma.sync.aligned.m16n8k16.row.col.f32.f16.f16.f32 " \
        "{%0,%1,%2,%3}, {%4,%5,%6,%7}, {%8,%9}, {%0,%1,%2,%3};" \
        : "+f"((d)[0]), "+f"((d)[1]), "+f"((d)[2]), "+f"((d)[3]) \
        : "r"((a)[0]), "r"((a)[1]), "r"((a)[2]), "r"((a)[3]), "r"((b)[0]), "r"((b)[1]))
#define CP_ASYNC16(dst, src) \
    asm volatile("cp.async.cg.shared.global [%0], [%1], 16;" :: "r"(dst), "l"(src) : "memory")
#define CP_COMMIT() asm volatile("cp.async.commit_group;" ::: "memory")
#define CP_WAIT(n)  asm volatile("cp.async.wait_group %0;" :: "n"(n) : "memory")

__device__ __forceinline__ float fsigm(float z) {
    return __fdividef(1.f, 1.f + __expf(-z));
}
__device__ __forceinline__ float ftanh(float x) {
    float xc = fminf(fmaxf(x, -15.f), 15.f);
    float e = __expf(2.f * xc);
    return __fdividef(e - 1.f, e + 1.f);
}

// ---------------------------------------------------------------------------
// Prep kernels
// ---------------------------------------------------------------------------
__global__ void split_x(const float* __restrict__ x) {
    size_t i = ((size_t)blockIdx.x * blockDim.x + threadIdx.x) * 4;
    float4 v = *(const float4*)(x + i);
    __half h[4] = {__float2half(v.x), __float2half(v.y),
                   __float2half(v.z), __float2half(v.w)};
    *(uint2*)&g_xh[i] = *(uint2*)h;
}

// W1 columns: ncol = blk*24 + g1*8 + hh ;  h = blk*8+hh ; gate = g1+1 (i,o,a)
__global__ void build_w1(const float* __restrict__ wr, const float* __restrict__ wi,
                         const float* __restrict__ wj, const float* __restrict__ wk,
                         const float* __restrict__ bx) {
    int idx = blockIdx.x * blockDim.x + threadIdx.x;  // over F_DIM * N1G
    int f = idx / N1G;
    int rem = idx - f * N1G;
    int blk = rem / 24;
    int r24 = rem - blk * 24;
    int g1 = r24 >> 3, hh = r24 & 7;
    int h = blk * 8 + hh;
    int gate = g1 + 1;                      // skip forget gate (index 0)
    int qout = h >> 6, h4 = h & 63;
    int qin = f >> 8, f4 = f & 255;
    const int   ci[4][4] = {{0,1,2,3},{1,0,3,2},{2,3,0,1},{3,2,1,0}};
    const float sg[4][4] = {{ 1.f, 1.f, 1.f, 1.f},
                            {-1.f, 1.f, 1.f,-1.f},
                            {-1.f,-1.f, 1.f, 1.f},
                            {-1.f, 1.f,-1.f, 1.f}};
    const float* arr[4] = {wr, wi, wj, wk};
    float v = arr[ci[qin][qout]][gate * (256 * 64) + f4 * 64 + h4] * sg[qin][qout];
    g_w1[f * N1G + rem] = __float2half(v);
    if (f == 0) g_b1[rem] = bx[gate * H_DIM + h];
}

__global__ void split_fco(const float* __restrict__ w) {
    int idx = blockIdx.x * blockDim.x + threadIdx.x;  // over 65536, [k][n]
    g_f2[idx] = __float2half(w[idx]);
}

// ---------------------------------------------------------------------------
// GEMM1 + LSTM epilogue: CTA 128x192, K-chunk 32, 8 warps 2x4 (warp 64x48),
// single fp16, 3-stage cp.async, 2 CTAs/SM.
// SMEM/stage: A[128][pitch 80B] = 10240 + B[32][pitch 400B] = 12800
// ---------------------------------------------------------------------------
#define G1_BOFF   10240
#define G1_STAGE  23040
#define G1_SMEM   (3 * G1_STAGE)

__global__ __launch_bounds__(256, 2)
void gemm1_lstm() {
    constexpr int KD = F_DIM, NSTEPS = KD / 32;
    extern __shared__ __align__(128) char smem[];
    const uint32_t sb = smem_u32(smem);
    const int tid = threadIdx.x, lane = tid & 31, wid = tid >> 5;
    const int wm = wid >> 2, wn = wid & 3;          // wm:0-1 (64 rows), wn:0-3 (48 cols)
    const int rowBase = blockIdx.y * 128, colBase = blockIdx.x * 192;

    // stage loader: A 512 chunks (16B) + B 768 chunks = 1280; 5/thread
    auto load_stage = [&](int buf, int k0) {
        uint32_t base = sb + buf * G1_STAGE;
#pragma unroll
        for (int i = 0; i < 5; i++) {
            int g = i * 256 + tid;
            const __half* src;
            uint32_t dst;
            if (g < 512) {                  // A: [128 rows][4 x 16B]
                int row = g >> 2, c16 = g & 3;
                src = g_xh + (size_t)(rowBase + row) * KD + k0 + c16 * 8;
                dst = base + row * 80 + c16 * 16;
            } else {                        // B: [32 rows][24 x 16B]
                int gb = g - 512;
                int row = gb / 24, c16 = gb - row * 24;
                src = g_w1 + (size_t)(k0 + row) * N1G + colBase + c16 * 8;
                dst = base + G1_BOFF + row * 400 + c16 * 16;
            }
            CP_ASYNC16(dst, src);
        }
        CP_COMMIT();
    };

    float acc[4][6][4];
#pragma unroll
    for (int a = 0; a < 4; a++)
#pragma unroll
        for (int b = 0; b < 6; b++)
#pragma unroll
            for (int c = 0; c < 4; c++) acc[a][b][c] = 0.f;

    load_stage(0, 0);
    load_stage(1, 32);

#pragma unroll 1
    for (int s = 0; s < NSTEPS; s++) {
        if (s + 1 < NSTEPS) CP_WAIT(1); else CP_WAIT(0);
        __syncthreads();
        if (s + 2 < NSTEPS) load_stage((s + 2) % 3, (s + 2) * 32);

        uint32_t base = sb + (s % 3) * G1_STAGE;
#pragma unroll
        for (int kk = 0; kk < 2; kk++) {
            uint32_t bf[3][4];
            uint32_t brow = base + G1_BOFF + (kk * 16 + (lane & 15)) * 400;
#pragma unroll
            for (int p = 0; p < 3; p++)
                LDSM_X4T(bf[p], brow + (wn * 48 + p * 16 + (lane >> 4) * 8) * 2);
#pragma unroll
            for (int mi = 0; mi < 4; mi++) {
                uint32_t af[4];
                LDSM_X4(af, base + (wm * 64 + mi * 16 + (lane & 15)) * 80
                            + (kk * 16 + (lane >> 4) * 8) * 2);
#pragma unroll
                for (int ni = 0; ni < 6; ni++)
                    MMA_F16(acc[mi][ni], af, &bf[ni >> 1][(ni & 1) * 2]);
            }
        }
    }

    // --------------------- LSTM epilogue (register-local) -------------------
    // ni 0..2 = gates {i,o,a} of h-block b0; ni 3..5 of block b0+1.
    const int c0 = 2 * (lane & 3);
    const int blk0 = (colBase / 24) + wn * 2;
#pragma unroll
    for (int b = 0; b < 2; b++) {
        const int cb = colBase + wn * 48 + b * 24;
        const int h0 = (blk0 + b) * 8 + c0;
        float bi0 = g_b1[cb + c0],      bi1 = g_b1[cb + c0 + 1];
        float bo0 = g_b1[cb + 8 + c0],  bo1 = g_b1[cb + 8 + c0 + 1];
        float ba0 = g_b1[cb + 16 + c0], ba1 = g_b1[cb + 16 + c0 + 1];
#pragma unroll
        for (int mi = 0; mi < 4; mi++) {
            int r0 = rowBase + wm * 64 + mi * 16 + (lane >> 2);
#pragma unroll
            for (int rr = 0; rr < 2; rr++) {
                float zi0 = acc[mi][3 * b + 0][rr * 2 + 0] + bi0;
                float zi1 = acc[mi][3 * b + 0][rr * 2 + 1] + bi1;
                float zo0 = acc[mi][3 * b + 1][rr * 2 + 0] + bo0;
                float zo1 = acc[mi][3 * b + 1][rr * 2 + 1] + bo1;
                float za0 = acc[mi][3 * b + 2][rr * 2 + 0] + ba0;
                float za1 = acc[mi][3 * b + 2][rr * 2 + 1] + ba1;
                float hv0 = fsigm(zo0) * ftanh(fsigm(zi0) * ftanh(za0));
                float hv1 = fsigm(zo1) * ftanh(fsigm(zi1) * ftanh(za1));
                size_t m = (size_t)(r0 + rr * 8);
                *(__half2*)&g_h[m * H_DIM + h0] =
                    __halves2half2(__float2half(hv0), __float2half(hv1));
            }
        }
    }
}

// ---------------------------------------------------------------------------
// GEMM2: out = H @ fco_w + fco_b. CTA 128x128, K=256, warp tile 64x32.
// SMEM/stage: A[128][80B] = 10240 + B[32][272B] = 8704
// ---------------------------------------------------------------------------
#define G2_BOFF   10240
#define G2_STAGE  18944
#define G2_SMEM   (3 * G2_STAGE)

__global__ __launch_bounds__(256, 2)
void gemm2(const float* __restrict__ biasg, float* __restrict__ outp) {
    constexpr int KD = H_DIM, NB = H_DIM, NSTEPS = KD / 32;
    extern __shared__ __align__(128) char smem[];
    const uint32_t sb = smem_u32(smem);
    const int tid = threadIdx.x, lane = tid & 31, wid = tid >> 5;
    const int wm = wid >> 2, wn = wid & 3;
    const int rowBase = blockIdx.y * 128, colBase = blockIdx.x * 128;

    auto load_stage = [&](int buf, int k0) {
        uint32_t base = sb + buf * G2_STAGE;
#pragma unroll
        for (int i = 0; i < 4; i++) {
            int g = i * 256 + tid;
            const __half* src;
            uint32_t dst;
            if (g < 512) {                  // A: [128 rows][4 x 16B]
                int row = g >> 2, c16 = g & 3;
                src = g_h + (size_t)(rowBase + row) * KD + k0 + c16 * 8;
                dst = base + row * 80 + c16 * 16;
            } else {                        // B: [32 rows][16 x 16B]
                int gb = g - 512;
                int row = gb >> 4, c16 = gb & 15;
                src = g_f2 + (size_t)(k0 + row) * NB + colBase + c16 * 8;
                dst = base + G2_BOFF + row * 272 + c16 * 16;
            }
            CP_ASYNC16(dst, src);
        }
        CP_COMMIT();
    };

    float acc[4][4][4];
#pragma unroll
    for (int a = 0; a < 4; a++)
#pragma unroll
        for (int b = 0; b < 4; b++)
#pragma unroll
            for (int c = 0; c < 4; c++) acc[a][b][c] = 0.f;

    load_stage(0, 0);
    load_stage(1, 32);

#pragma unroll 1
    for (int s = 0; s < NSTEPS; s++) {
        if (s + 1 < NSTEPS) CP_WAIT(1); else CP_WAIT(0);
        __syncthreads();
        if (s + 2 < NSTEPS) load_stage((s + 2) % 3, (s + 2) * 32);

        uint32_t base = sb + (s % 3) * G2_STAGE;
#pragma unroll
        for (int kk = 0; kk < 2; kk++) {
            uint32_t bf[2][4];
#pragma unroll
            for (int p = 0; p < 2; p++)
                LDSM_X4T(bf[p], base + G2_BOFF + (kk * 16 + (lane & 15)) * 272
                               + (wn * 32 + p * 16 + (lane >> 4) * 8) * 2);
#pragma unroll
            for (int mi = 0; mi < 4; mi++) {
                uint32_t af[4];
                LDSM_X4(af, base + (wm * 64 + mi * 16 + (lane & 15)) * 80
                            + (kk * 16 + (lane >> 4) * 8) * 2);
#pragma unroll
                for (int ni = 0; ni < 4; ni++)
                    MMA_F16(acc[mi][ni], af, &bf[ni >> 1][(ni & 1) * 2]);
            }
        }
    }

#pragma unroll
    for (int mi = 0; mi < 4; mi++) {
        int r0 = rowBase + wm * 64 + mi * 16 + (lane >> 2);
#pragma unroll
        for (int ni = 0; ni < 4; ni++) {
            int col = colBase + wn * 32 + ni * 8 + (lane & 3) * 2;
            float b0 = biasg[col], b1 = biasg[col + 1];
            float2 o0 = {acc[mi][ni][0] + b0, acc[mi][ni][1] + b1};
            float2 o1 = {acc[mi][ni][2] + b0, acc[mi][ni][3] + b1};
            *(float2*)&outp[(size_t)r0 * NB + col] = o0;
            *(float2*)&outp[(size_t)(r0 + 8) * NB + col] = o1;
        }
    }
}

// ---------------------------------------------------------------------------
extern "C" void kernel_launch(void* const* d_in, const int* in_sizes, int n_in,
                              void* d_out, int out_size) {
    const float* x     = (const float*)d_in[0];
    const float* wx_r  = (const float*)d_in[1];
    const float* wx_i  = (const float*)d_in[2];
    const float* wx_j  = (const float*)d_in[3];
    const float* wx_k  = (const float*)d_in[4];
    const float* bx    = (const float*)d_in[5];
    const float* fco_w = (const float*)d_in[10];
    const float* fco_b = (const float*)d_in[11];
    float* out = (float*)d_out;

    split_x<<<(B_DIM * F_DIM / 4) / 256, 256>>>(x);
    build_w1<<<(F_DIM * N1G) / 256, 256>>>(wx_r, wx_i, wx_j, wx_k, bx);
    split_fco<<<(H_DIM * H_DIM) / 256, 256>>>(fco_w);

    cudaFuncSetAttribute(gemm1_lstm,
                         cudaFuncAttributeMaxDynamicSharedMemorySize, G1_SMEM);
    cudaFuncSetAttribute(gemm2,
                         cudaFuncAttributeMaxDynamicSharedMemorySize, G2_SMEM);

    gemm1_lstm<<<dim3(N1G / 192, B_DIM / 128), 256, G1_SMEM>>>();
    gemm2<<<dim3(H_DIM / 128, B_DIM / 128), 256, G2_SMEM>>>(fco_b, out);
}